// round 12
// baseline (speedup 1.0000x reference)
#include <cuda_runtime.h>

#define TT      64
#define NB      16
#define CC      256
#define DOUT    129
#define THREADS 256
#define BPB     2                          // bids per block
#define TSTRIDE (NB * CC * DOUT)           // floats between consecutive t planes

#define LOG2E_HALF 0.72134752044448169f    // 0.5*log2(e); a^k = 2^(-k*LOG2E_HALF)

// Shift-copy placement (floats) inside each channel's table.
// pos[s] mod 32 = {20, 0, 8, 16} for s = {0,1,2,3} -> conflict-free LDS.128
__device__ __forceinline__ int copy_pos(int s) {
    return (s == 0) ? 628 : (s * 200 - 200);   // s=1->0, s=2->200, s=3->400, s=0->628
}

__global__ __launch_bounds__(THREADS, 6)
void jeffress_kernel(const float2* __restrict__ inp,         // (T, N*C) float2 over last dim
                     const float*  __restrict__ delay_param, // (129)
                     const float*  __restrict__ weight,      // scalar
                     const float2* __restrict__ u,           // (N*C, 129) float2 over last dim
                     float*        __restrict__ out)         // (T, N*C, 129)
{
    __shared__ float xs[BPB][2][64];
    __shared__ float S[BPB][2][64];
    __shared__ float P[65];
    __shared__ __align__(16) float Ctab[BPB][2][832];   // 4 shifted copies per (bid,ch)
    __shared__ int   Lsh[BPB][2];
    __shared__ float S63sh[BPB][2];

    const int tid  = threadIdx.x;
    const int b0   = blockIdx.x * BPB;
    const int bidL = tid >> 7;            // which of the 2 bids this thread emits for
    const int dd   = tid & 127;

    // ---- prefetch per-thread emit inputs early ----
    const float  dp = delay_param[dd];
    const float2 uu = u[(b0 + bidL) * DOUT + dd];

    // ---- stage both bids' 64-step series ----
    if (tid < BPB * 64) {
        const int bl = tid >> 6, t = tid & 63;
        float2 v = inp[t * (NB * CC) + b0 + bl];
        xs[bl][0][t] = v.x;
        xs[bl][1][t] = v.y;
    }
    // ---- decay powers P[k] = a^k, k in [0,64] ----
    if (tid >= 128 && tid < 128 + 65) {
        int k = tid - 128;
        P[k] = exp2f(-LOG2E_HALF * (float)k);
    }
    __syncthreads();

    // ---- parallel serial scans: 4 lanes = (bid,ch); FIRST argmax ----
    if (tid < BPB * 2) {
        const int bl = tid >> 1, ch = tid & 1;
        const float a = 0.60653065971263342f;   // exp(-0.5)
        float v = 0.f, best = -1.f;
        int bt = 0;
        #pragma unroll
        for (int t = 0; t < 64; t++) {
            float x = xs[bl][ch][t];
            v = v * a + x;
            S[bl][ch][t] = v;
            if (x > best) { best = x; bt = t; }  // strict '>' => first max
        }
        Lsh[bl][ch]   = 63 - bt;
        S63sh[bl][ch] = v;
    }
    __syncthreads();

    const float W = *weight;

    // ---- build 4 shift-aligned copies per (bid,ch):
    //      Ctab[bl][ch][pos[s]+i] = U(i+s)
    //      U(q) = S[q-64]*W                    for  65 <= q < 128  (t <  d)
    //      U(q) = (S[q-128]+P[q-127]*S63)*W    for 128 <= q < 192  (t >= d)
    #pragma unroll
    for (int cs = 0; cs < BPB * 2 * 4; cs++) {
        const int bl = cs >> 3, ch = (cs >> 2) & 1, s = cs & 3;
        const int pos = copy_pos(s);
        const float S63 = S63sh[bl][ch];
        const int i = 62 + tid;                   // 62..317 covers needed 62..191
        if (i < 192) {
            int q = i + s;
            float v = 0.f;
            if (q >= 65 && q < 128)       v = S[bl][ch][q - 64] * W;
            else if (q >= 128 && q < 192) v = fmaf(P[q - 127], S63, S[bl][ch][q - 128]) * W;
            Ctab[bl][ch][pos + i] = v;
        }
    }
    __syncthreads();

    // ---- per-thread constants for (bidL, dd) ----
    const float L0 = (float)Lsh[bidL][0], L1 = (float)Lsh[bidL][1];
    float del0 = fmaxf(dp, 0.f),  del1 = fmaxf(-dp, 0.f);
    float df0  = floorf(del0),    df1  = floorf(del1);
    float r0 = (uu.x < del0 - df0) ? df0 + 1.f : df0;
    float r1 = (uu.y < del1 - df1) ? df1 + 1.f : df1;
    r0 = fminf(r0, L0);  r1 = fminf(r1, L1);
    const int d0 = min(63, max(0, (int)r0));
    const int d1 = min(63, max(0, (int)r1));
    const float ncm = -(S[bidL][0][63 - d0] + S[bidL][1][63 - d1]) * W;

    const int s0 = (-d0) & 3, s1 = (-d1) & 3;
    const int bi0 = copy_pos(s0) + (128 - d0 - s0);   // multiple of 4 -> 16B aligned
    const int bi1 = copy_pos(s1) + (128 - d1 - s1);
    const float4* A4 = (const float4*)&Ctab[bidL][0][bi0];
    const float4* B4 = (const float4*)&Ctab[bidL][1][bi1];

    const float a  = 0.60653065971263342f;
    const float a2 = a * a, a3 = a2 * a, a4 = a2 * a2;
    const float n0 = ncm * a, n1 = ncm * a2, n2 = ncm * a3, n3 = ncm * a4;
    float ptb = 1.0f;                                 // a^{4g}
    float* outp = out + (b0 + bidL) * DOUT + dd;      // 32-bit offsets throughout

    // ---- emit 64 outputs: f(t) = U0[t] + U1[t] + a^{t+1}*ncm ----
    #pragma unroll 4
    for (int g = 0; g < 16; g++) {
        float4 A = A4[g];
        float4 B = B4[g];
        outp[0]           = fmaf(ptb, n0, A.x + B.x);
        outp[TSTRIDE]     = fmaf(ptb, n1, A.y + B.y);
        outp[2 * TSTRIDE] = fmaf(ptb, n2, A.z + B.z);
        outp[3 * TSTRIDE] = fmaf(ptb, n3, A.w + B.w);
        ptb *= a4;
        outp += 4 * TSTRIDE;
    }

    // ---- tail: dd = 128, (bid, t) per thread ----
    if (tid < BPB * 64) {
        const int bl = tid >> 6, t = tid & 63;
        const float  dpL = delay_param[DOUT - 1];
        const float2 uL  = u[(b0 + bl) * DOUT + (DOUT - 1)];
        const float tL0 = (float)Lsh[bl][0], tL1 = (float)Lsh[bl][1];
        float e0f = fmaxf(dpL, 0.f), e1f = fmaxf(-dpL, 0.f);
        float f0  = floorf(e0f),     f1  = floorf(e1f);
        float q0 = (uL.x < e0f - f0) ? f0 + 1.f : f0;
        float q1 = (uL.y < e1f - f1) ? f1 + 1.f : f1;
        q0 = fminf(q0, tL0);  q1 = fminf(q1, tL1);
        const int e0 = min(63, max(0, (int)q0));
        const int e1 = min(63, max(0, (int)q1));
        const float nc = -(S[bl][0][63 - e0] + S[bl][1][63 - e1]) * W;
        // copy s=1 sits at pos 0: Ctab[..][i] = U(i+1) -> i = (128-e+t)-1
        float v0 = Ctab[bl][0][127 - e0 + t];
        float v1 = Ctab[bl][1][127 - e1 + t];
        out[t * TSTRIDE + (b0 + bl) * DOUT + 128] = fmaf(P[t + 1], nc, v0 + v1);
    }
}

extern "C" void kernel_launch(void* const* d_in, const int* in_sizes, int n_in,
                              void* d_out, int out_size)
{
    const void* p_input = d_in[0];
    const void* p_delay = d_in[1];
    const void* p_w     = d_in[2];
    const void* p_u     = d_in[3];
    for (int i = 0; i < n_in; i++) {
        if (in_sizes[i] == TT * NB * CC * 2)        p_input = d_in[i];
        else if (in_sizes[i] == DOUT)               p_delay = d_in[i];
        else if (in_sizes[i] == 1)                  p_w     = d_in[i];
        else if (in_sizes[i] == NB * CC * DOUT * 2) p_u     = d_in[i];
    }

    jeffress_kernel<<<(NB * CC) / BPB, THREADS>>>(
        (const float2*)p_input,
        (const float*)p_delay,
        (const float*)p_w,
        (const float2*)p_u,
        (float*)d_out);
}

// round 14
// speedup vs baseline: 1.3385x; 1.3385x over previous
#include <cuda_runtime.h>

#define TT       64
#define NBID     4096                    // N*C
#define DOUT     129
#define BPB      32                      // bids per block: 32*516B = 129 full lines
#define THREADS  1024
#define TSTRIDE  (NBID * DOUT)           // floats between consecutive t planes
#define FLAT     (BPB * DOUT)            // 4128 outputs per t-plane per block

#define LOG2E_HALF 0.72134752044448169f  // 0.5*log2(e)

// dynamic smem layout (floats):
//   [0,8256)      Utab[64 pairs][129]   (xs overlaid here during load/scan)
//   [8256,12352)  S_t[64 t][64 pairs]
//   [12352,12417) P[65]
//   [12417,12546) dly[129]
//   [12546,12610) S63sh[64]
//   [12610,12674) Lsh[64] (int)
#define SMEM_FLOATS 12674
#define SMEM_BYTES  (SMEM_FLOATS * 4)

__global__ void __launch_bounds__(THREADS, 1)
jeffress_kernel(const float2* __restrict__ inp,         // (T, N*C) float2 over last dim
                const float*  __restrict__ delay_param, // (129)
                const float*  __restrict__ weight,      // scalar
                const float2* __restrict__ u,           // (N*C, 129) float2 over last dim
                float*        __restrict__ out)         // (T, N*C, 129)
{
    extern __shared__ float sm[];
    float* Utab  = sm;                 // 8256 floats; xs (4096 floats) overlaid at front
    float* S_t   = sm + 8256;          // 4096
    float* P     = sm + 12352;         // 65
    float* dly   = sm + 12417;         // 129
    float* S63sh = sm + 12546;         // 64
    int*   Lsh   = (int*)(sm + 12610); // 64

    const int tid = threadIdx.x;
    const int b0  = blockIdx.x * BPB;

    // ---- stage 32 bids' 64-step series: xs2[t*32+bl] (overlaid in Utab area) ----
    {
        float2* xs2 = (float2*)Utab;
        int e2 = tid;
        #pragma unroll
        for (int r = 0; r < 2; r++, e2 += THREADS) {   // 2048 float2 loads
            int t = e2 >> 5, bl = e2 & 31;
            xs2[t * 32 + bl] = inp[t * NBID + b0 + bl]; // 256B contiguous per warp
        }
    }
    if (tid < 65) P[tid] = exp2f(-LOG2E_HALF * (float)tid);
    if (tid >= 65 && tid < 65 + DOUT) dly[tid - 65] = delay_param[tid - 65];
    __syncthreads();

    // ---- 64 parallel LIF scans + FIRST argmax: lane = pair = 2*bid + ch ----
    if (tid < 64) {
        const float a = 0.60653065971263342f;   // exp(-0.5)
        const float* xsf = Utab;                // xs[t*64 + pair]
        float v = 0.f, best = -1.f;
        int bt = 0;
        #pragma unroll
        for (int t = 0; t < TT; t++) {
            float x = xsf[t * 64 + tid];
            v = v * a + x;
            S_t[t * 64 + tid] = v;
            if (x > best) { best = x; bt = t; }  // strict '>' => first max (jnp.argmax)
        }
        Lsh[tid]   = 63 - bt;
        S63sh[tid] = v;
    }
    __syncthreads();

    const float W = *weight;

    // ---- build Utab[pair][i], i in [0,128):
    //      i in [1,64):   U = S[i]*W                     (t <  d regime)
    //      i in [64,128): U = (S[i-64] + P[i-63]*S63)*W  (t >= d regime)
    {
        const int pair = tid & 63, i0 = tid >> 6;       // i0 in [0,16)
        const float S63 = S63sh[pair];
        #pragma unroll
        for (int k = 0; k < 8; k++) {
            int i = i0 + k * 16;
            float v;
            if (i < 64) v = (i >= 1) ? S_t[i * 64 + pair] * W : 0.f;
            else        v = fmaf(P[i - 63], S63, S_t[(i - 64) * 64 + pair]) * W;
            Utab[pair * 129 + i] = v;                   // 129 stride: conflict-free
        }
    }
    __syncthreads();

    // ---- emit: flat mapping. thread covers flat positions e = j*1024 + tid.
    //      Every warp store = one fully-covered, 128B-aligned line. ----
    const float a  = 0.60653065971263342f;
    const float m1 = a, m2 = a * a, m3 = m2 * a, m4 = m2 * m2;

    const int nj = (tid < FLAT - 4 * THREADS) ? 5 : 4;  // 32 leftover -> warp 0, j=4
    int e = tid;
    for (int j = 0; j < nj; j++, e += THREADS) {
        const unsigned eu  = (unsigned)e;
        const unsigned bid = eu / 129u;                 // const-div -> mul+shift
        const unsigned dd  = eu - bid * 129u;

        // per-(bid,dd) delay rounding + clamp (amortized over 64 outputs)
        const float  dp = dly[dd];
        const float2 uu = u[b0 * DOUT + e];             // coalesced float2
        float del0 = fmaxf(dp, 0.f), del1 = fmaxf(-dp, 0.f);
        float df0  = floorf(del0),   df1  = floorf(del1);
        float r0 = (uu.x < del0 - df0) ? df0 + 1.f : df0;
        float r1 = (uu.y < del1 - df1) ? df1 + 1.f : df1;
        r0 = fminf(r0, (float)Lsh[2 * bid]);
        r1 = fminf(r1, (float)Lsh[2 * bid + 1]);
        const int d0 = min(63, max(0, (int)r0));
        const int d1 = min(63, max(0, (int)r1));
        const float ncm = -(S_t[(63 - d0) * 64 + 2 * bid] +
                            S_t[(63 - d1) * 64 + 2 * bid + 1]) * W;

        const float* A = Utab + bid * 258 + (64 - d0);        // index by t, linear
        const float* B = Utab + bid * 258 + 129 + (64 - d1);
        float* op = out + b0 * DOUT + e;

        float acc = ncm;                                      // acc*a^k ladder
        #pragma unroll
        for (int t4 = 0; t4 < TT; t4 += 4) {
            float v0 = A[t4 + 0] + B[t4 + 0];
            float v1 = A[t4 + 1] + B[t4 + 1];
            float v2 = A[t4 + 2] + B[t4 + 2];
            float v3 = A[t4 + 3] + B[t4 + 3];
            op[0]           = fmaf(acc, m1, v0);   // f(t) = U0+U1 + a^{t+1}*ncm
            op[TSTRIDE]     = fmaf(acc, m2, v1);
            op[2 * TSTRIDE] = fmaf(acc, m3, v2);
            op[3 * TSTRIDE] = fmaf(acc, m4, v3);
            acc *= m4;
            op += 4 * TSTRIDE;
        }
    }
}

extern "C" void kernel_launch(void* const* d_in, const int* in_sizes, int n_in,
                              void* d_out, int out_size)
{
    const void* p_input = d_in[0];
    const void* p_delay = d_in[1];
    const void* p_w     = d_in[2];
    const void* p_u     = d_in[3];
    for (int i = 0; i < n_in; i++) {
        if (in_sizes[i] == TT * NBID * 2)        p_input = d_in[i];
        else if (in_sizes[i] == DOUT)            p_delay = d_in[i];
        else if (in_sizes[i] == 1)               p_w     = d_in[i];
        else if (in_sizes[i] == NBID * DOUT * 2) p_u     = d_in[i];
    }

    static int attr_done = 0;
    if (!attr_done) {
        cudaFuncSetAttribute(jeffress_kernel,
                             cudaFuncAttributeMaxDynamicSharedMemorySize, SMEM_BYTES);
        attr_done = 1;
    }

    jeffress_kernel<<<NBID / BPB, THREADS, SMEM_BYTES>>>(
        (const float2*)p_input,
        (const float*)p_delay,
        (const float*)p_w,
        (const float2*)p_u,
        (float*)d_out);
}